// round 6
// baseline (speedup 1.0000x reference)
#include <cuda_runtime.h>
#include <cuda_bf16.h>
#include <math.h>
#include <stdint.h>

// ---------------- problem constants ----------------
#define CDIM   96
#define DD     32
#define HH     64
#define WWD    64
#define BATCH  2
#define SP     131072
#define NTOK   (BATCH * SP)
#define NWIN   2048
#define NHEAD  4
#define HDIM   24
#define NWT    64

// ---------------- device scratch ----------------
__device__ __nv_bfloat16 g_xw  [(size_t)NTOK * CDIM];      // LN1'd, window-major
__device__ float         g_xres[(size_t)NTOK * CDIM];      // raw rolled x, window-major
__device__ __nv_bfloat16 g_qkv [(size_t)NTOK * 3 * CDIM];  // window-major
__device__ __nv_bfloat16 g_att [(size_t)NTOK * CDIM];      // window-major
__device__ float         g_x2  [(size_t)NTOK * CDIM];      // residual, SPATIAL token-major
__device__ __nv_bfloat16 g_hn  [(size_t)NTOK * CDIM];      // LN2 out, SPATIAL token-major
// bf16 weights
__device__ __nv_bfloat16 g_wqkv[288 * 96];
__device__ __nv_bfloat16 g_wproj[96 * 96];
__device__ __nv_bfloat16 g_wfc1[384 * 96];
__device__ __nv_bfloat16 g_wfc2[96 * 384];

__device__ __forceinline__ uint32_t packbf(float a, float b) {
    __nv_bfloat162 h = __floats2bfloat162_rn(a, b);
    return *reinterpret_cast<uint32_t*>(&h);
}
__device__ __forceinline__ float2 unpackbf(uint32_t u) {
    return __bfloat1622float2(*reinterpret_cast<const __nv_bfloat162*>(&u));
}

__global__ void k_wconv(const float* __restrict__ a, const float* __restrict__ b,
                        const float* __restrict__ c, const float* __restrict__ d)
{
    int i = blockIdx.x * 256 + threadIdx.x;
    if (i < 27648)            g_wqkv[i]          = __float2bfloat16_rn(a[i]);
    else if (i < 36864)       g_wproj[i - 27648] = __float2bfloat16_rn(b[i - 27648]);
    else if (i < 73728)       g_wfc1[i - 36864]  = __float2bfloat16_rn(c[i - 36864]);
    else if (i < 110592)      g_wfc2[i - 73728]  = __float2bfloat16_rn(d[i - 73728]);
}

// ============================================================
// K0: LN1 + roll + window partition. Coalesced spatial read,
// writes g_xw (bf16, LN'd) and g_xres (f32 raw), window-major.
// ============================================================
__global__ void k_pre(const float* __restrict__ x,
                      const float* __restrict__ gw,
                      const float* __restrict__ gb)
{
    __shared__ float sm[CDIM][33];
    __shared__ float s_mean[32], s_rstd[32];
    __shared__ int   s_row[32];

    int blk = blockIdx.x;
    int wt  = blk & 1;
    int h   = (blk >> 1) & 63;
    int d   = (blk >> 7) & 31;
    int b   = blk >> 12;
    int w0  = wt * 32;
    int tid = threadIdx.x;   // 128

    const float* xb = x + (size_t)b * CDIM * SP + (size_t)d * 4096 + h * 64 + w0;
    for (int i = tid; i < CDIM * 32; i += 128) {
        int c = i >> 5, t = i & 31;
        sm[c][t] = xb[(size_t)c * SP + t];
    }
    __syncthreads();

    if (tid < 32) {
        float s = 0.f, ss = 0.f;
        #pragma unroll
        for (int c = 0; c < CDIM; c++) { float v = sm[c][tid]; s += v; ss += v * v; }
        float mean = s * (1.f / CDIM);
        s_mean[tid] = mean;
        s_rstd[tid] = rsqrtf(ss * (1.f / CDIM) - mean * mean + 1e-5f);
        int w  = w0 + tid;
        int ds = (d + DD - 2) & (DD - 1);
        int hs = (h + HH - 2) & (HH - 1);
        int ws = (w + WWD - 2) & (WWD - 1);
        int widx  = ((ds >> 2) * 16 + (hs >> 2)) * 16 + (ws >> 2);
        int inner = ((ds & 3) * 16) + ((hs & 3) * 4) + (ws & 3);
        s_row[tid] = (b * NWIN + widx) * NWT + inner;
    }
    __syncthreads();

    for (int i = tid; i < 32 * CDIM; i += 128) {
        int t = i / CDIM, c = i - t * CDIM;
        float v = sm[c][t];
        size_t row = (size_t)s_row[t];
        g_xres[row * CDIM + c] = v;
        g_xw[row * CDIM + c] =
            __float2bfloat16_rn((v - s_mean[t]) * s_rstd[t] * gw[c] + gb[c]);
    }
}

// ---------------- mma helpers (M=128, K=96 single-shot, pitch 52 u32) ----------------
#define PITCH 52

__device__ __forceinline__ void mma_bf16(float c[4], const uint32_t a[4], const uint32_t b[2]) {
    asm volatile(
        "mma.sync.aligned.m16n8k16.row.col.f32.bf16.bf16.f32 "
        "{%0,%1,%2,%3}, {%4,%5,%6,%7}, {%8,%9}, {%0,%1,%2,%3};\n"
        : "+f"(c[0]), "+f"(c[1]), "+f"(c[2]), "+f"(c[3])
        : "r"(a[0]), "r"(a[1]), "r"(a[2]), "r"(a[3]), "r"(b[0]), "r"(b[1]));
}

__device__ __forceinline__ void mma_tile96(const uint32_t* As, const uint32_t* Bs,
                                           float acc[2][6][4], int g, int t4, int wm, int wn)
{
    #pragma unroll
    for (int ks = 0; ks < 6; ks++) {
        int k8 = ks * 8;
        uint32_t af[2][4];
        #pragma unroll
        for (int mt = 0; mt < 2; mt++) {
            int rb = wm * 32 + mt * 16;
            af[mt][0] = As[(rb + g    ) * PITCH + k8 + t4    ];
            af[mt][1] = As[(rb + g + 8) * PITCH + k8 + t4    ];
            af[mt][2] = As[(rb + g    ) * PITCH + k8 + t4 + 4];
            af[mt][3] = As[(rb + g + 8) * PITCH + k8 + t4 + 4];
        }
        uint32_t bf[6][2];
        #pragma unroll
        for (int nt = 0; nt < 6; nt++) {
            int nb = wn * 48 + nt * 8;
            bf[nt][0] = Bs[(nb + g) * PITCH + k8 + t4    ];
            bf[nt][1] = Bs[(nb + g) * PITCH + k8 + t4 + 4];
        }
        #pragma unroll
        for (int mt = 0; mt < 2; mt++)
            #pragma unroll
            for (int nt = 0; nt < 6; nt++)
                mma_bf16(acc[mt][nt], af[mt], bf[nt]);
    }
}

__device__ __forceinline__ void stage_A96(const __nv_bfloat16* A, size_t bm, uint32_t* As, int tid) {
    for (int i = tid; i < 128 * 12; i += 256) {
        int row = i / 12, q = i - row * 12;
        ((uint4*)&As[row * PITCH])[q] = ((const uint4*)(A + (bm + row) * 96))[q];
    }
}
__device__ __forceinline__ void stage_B96(const __nv_bfloat16* Wb, int bn, uint32_t* Bs, int tid) {
    for (int i = tid; i < 96 * 12; i += 256) {
        int row = i / 12, q = i - row * 12;
        ((uint4*)&Bs[row * PITCH])[q] = ((const uint4*)(Wb + (size_t)(bn + row) * 96))[q];
    }
}

// window-major row r -> spatial token index
__device__ __forceinline__ int decode_spatial(int r, int& b) {
    int widx = r >> 6, inner = r & 63;
    b = widx >> 11;
    int wi = widx & 2047;
    int wd = wi >> 8, wh = (wi >> 4) & 15, ww = wi & 15;
    int d = (wd * 4 + (inner >> 4) + 2) & 31;
    int h = (wh * 4 + ((inner >> 2) & 3) + 2) & 63;
    int w = (ww * 4 + (inner & 3) + 2) & 63;
    return d * 4096 + h * 64 + w;
}

// ============================================================
// K1: qkv GEMM (pure, coalesced A; 3 N-tiles in-block)
// ============================================================
__global__ void __launch_bounds__(256)
k_qkv(const float* __restrict__ qbias)
{
    extern __shared__ char smem[];
    uint32_t* As = (uint32_t*)smem;            // 26624B
    uint32_t* Bs = (uint32_t*)(smem + 26624);  // 19968B

    int tid = threadIdx.x;
    size_t bm = (size_t)blockIdx.x * 128;
    stage_A96(g_xw, bm, As, tid);

    int warp = tid >> 5, lane = tid & 31, g = lane >> 2, t4 = lane & 3;
    int wm = warp >> 1, wn = warp & 1;

    for (int bt = 0; bt < 3; bt++) {
        if (bt) __syncthreads();
        stage_B96(g_wqkv, bt * 96, Bs, tid);
        __syncthreads();
        float acc[2][6][4];
        #pragma unroll
        for (int i = 0; i < 2; i++)
            #pragma unroll
            for (int j = 0; j < 6; j++)
                #pragma unroll
                for (int r = 0; r < 4; r++) acc[i][j][r] = 0.f;
        mma_tile96(As, Bs, acc, g, t4, wm, wn);
        #pragma unroll
        for (int mt = 0; mt < 2; mt++)
            #pragma unroll
            for (int nt = 0; nt < 6; nt++) {
                int ncol = wn * 48 + nt * 8 + t4 * 2;
                #pragma unroll
                for (int half = 0; half < 2; half++) {
                    size_t row = bm + wm * 32 + mt * 16 + g + half * 8;
                    float v0 = acc[mt][nt][half * 2 + 0] + qbias[bt * 96 + ncol];
                    float v1 = acc[mt][nt][half * 2 + 1] + qbias[bt * 96 + ncol + 1];
                    *(uint32_t*)&g_qkv[row * 288 + bt * 96 + ncol] = packbf(v0, v1);
                }
            }
    }
}

// ============================================================
// K2: windowed attention (f32 K/V in smem, float4 inner loop)
// ============================================================
__global__ void __launch_bounds__(256)
k_attn(const float* __restrict__ rpb)
{
    extern __shared__ char smem[];
    float* kk   = (float*)smem;
    float* vv   = kk + 4 * 64 * 24;
    float* bcol = vv + 4 * 64 * 24;
    int*   gtok = (int*)(bcol + 4 * 344);

    int bn  = blockIdx.x;
    int tid = threadIdx.x;
    int hh  = tid >> 6;
    int tok = tid & 63;

    const uint32_t* qkvb = (const uint32_t*)(g_qkv + (size_t)bn * NWT * 288);

    for (int i = tid; i < 4 * 64 * 12; i += 256) {
        int hph = i / 768;
        int rem = i - hph * 768;
        int j = rem / 12, p = rem - j * 12;
        const uint32_t* base = qkvb + j * 144;
        float2 kf = unpackbf(base[48 + hph * 12 + p]);
        float2 vf = unpackbf(base[96 + hph * 12 + p]);
        kk[(hph * 64 + j) * 24 + 2 * p    ] = kf.x;
        kk[(hph * 64 + j) * 24 + 2 * p + 1] = kf.y;
        vv[(hph * 64 + j) * 24 + 2 * p    ] = vf.x;
        vv[(hph * 64 + j) * 24 + 2 * p + 1] = vf.y;
    }
    for (int i = tid; i < 4 * 343; i += 256) {
        int hph = i / 343, r = i - hph * 343;
        bcol[hph * 344 + r] = rpb[r * NHEAD + hph];
    }
    if (tid < NWT) {
        int widx = bn & (NWIN - 1);
        int wd = widx >> 8, wh = (widx >> 4) & 15, ww = widx & 15;
        int id = tid >> 4, ih = (tid >> 2) & 3, iw = tid & 3;
        int da = wd * 4 + id, ha = wh * 4 + ih, wa = ww * 4 + iw;
        int rd = (da < DD  - 4) ? 0 : ((da < DD  - 2) ? 1 : 2);
        int rh = (ha < HH  - 4) ? 0 : ((ha < HH  - 2) ? 1 : 2);
        int rw = (wa < WWD - 4) ? 0 : ((wa < WWD - 2) ? 1 : 2);
        gtok[tid] = rd * 9 + rh * 3 + rw;
    }

    float q[HDIM];
    {
        const uint32_t* base = qkvb + tok * 144;
        #pragma unroll
        for (int p = 0; p < 12; p++) {
            float2 f = unpackbf(base[hh * 12 + p]);
            q[2 * p    ] = f.x * 0.2041241452319315f;
            q[2 * p + 1] = f.y * 0.2041241452319315f;
        }
    }
    __syncthreads();

    int id = tok >> 4, ih = (tok >> 2) & 3, iw = tok & 3;
    int mygrp = gtok[tok];
    const float* bch = bcol + hh * 344;
    const float4* kf4 = (const float4*)(kk + hh * 64 * 24);
    const float4* vf4 = (const float4*)(vv + hh * 64 * 24);

    float o[HDIM];
    #pragma unroll
    for (int dd = 0; dd < HDIM; dd++) o[dd] = 0.f;
    float sum = 0.f;

    #pragma unroll 4
    for (int j = 0; j < NWT; j++) {
        const float4* kr = kf4 + j * 6;
        float a = 0.f;
        #pragma unroll
        for (int p = 0; p < 6; p++) {
            float4 kv = kr[p];
            a = fmaf(q[4 * p    ], kv.x, a);
            a = fmaf(q[4 * p + 1], kv.y, a);
            a = fmaf(q[4 * p + 2], kv.z, a);
            a = fmaf(q[4 * p + 3], kv.w, a);
        }
        int jd = j >> 4, jh = (j >> 2) & 3, jw = j & 3;
        a += bch[(id - jd + 3) * 49 + (ih - jh + 3) * 7 + (iw - jw + 3)];
        float e = (gtok[j] == mygrp) ? __expf(a) : 0.f;
        sum += e;
        const float4* vr = vf4 + j * 6;
        #pragma unroll
        for (int p = 0; p < 6; p++) {
            float4 vvec = vr[p];
            o[4 * p    ] = fmaf(e, vvec.x, o[4 * p    ]);
            o[4 * p + 1] = fmaf(e, vvec.y, o[4 * p + 1]);
            o[4 * p + 2] = fmaf(e, vvec.z, o[4 * p + 2]);
            o[4 * p + 3] = fmaf(e, vvec.w, o[4 * p + 3]);
        }
    }
    float inv = 1.f / sum;

    uint32_t* op = (uint32_t*)(g_att + ((size_t)bn * NWT + tok) * CDIM + hh * HDIM);
    #pragma unroll
    for (int p = 0; p < 12; p++)
        op[p] = packbf(o[2 * p] * inv, o[2 * p + 1] * inv);
}

// ============================================================
// K3: proj GEMM + residual (coalesced g_xres) + LN2
// writes g_x2 (f32) and g_hn (bf16), SPATIAL token-major
// ============================================================
__global__ void __launch_bounds__(256)
k_proj(const float* __restrict__ pbias,
       const float* __restrict__ g2, const float* __restrict__ b2)
{
    extern __shared__ char smem[];
    uint32_t* As = (uint32_t*)smem;
    uint32_t* Bs = (uint32_t*)(smem + 26624);
    float* xs    = (float*)smem;                  // [128][97], reuses As/Bs
    int*   sprow = (int*)(smem + 49664);
    float* smu   = (float*)(smem + 50176);
    float* srs   = (float*)(smem + 50688);
    float* sg2   = (float*)(smem + 51200);
    float* sb2   = (float*)(smem + 51584);

    int tid = threadIdx.x;
    if (tid < 96) { sg2[tid] = g2[tid]; sb2[tid] = b2[tid]; }

    size_t bm = (size_t)blockIdx.x * 128;
    stage_A96(g_att, bm, As, tid);
    stage_B96(g_wproj, 0, Bs, tid);
    __syncthreads();

    int warp = tid >> 5, lane = tid & 31, g = lane >> 2, t4 = lane & 3;
    int wm = warp >> 1, wn = warp & 1;

    float acc[2][6][4];
    #pragma unroll
    for (int i = 0; i < 2; i++)
        #pragma unroll
        for (int j = 0; j < 6; j++)
            #pragma unroll
            for (int r = 0; r < 4; r++) acc[i][j][r] = 0.f;
    mma_tile96(As, Bs, acc, g, t4, wm, wn);
    __syncthreads();

    #pragma unroll
    for (int mt = 0; mt < 2; mt++)
        #pragma unroll
        for (int nt = 0; nt < 6; nt++) {
            int cl = wn * 48 + nt * 8 + t4 * 2;
            #pragma unroll
            for (int half = 0; half < 2; half++) {
                int rl = wm * 32 + mt * 16 + g + half * 8;
                xs[rl * 97 + cl    ] = acc[mt][nt][half * 2 + 0] + pbias[cl];
                xs[rl * 97 + cl + 1] = acc[mt][nt][half * 2 + 1] + pbias[cl + 1];
            }
        }
    __syncthreads();

    // coalesced residual from g_xres (window-major, same rows)
    for (int i = tid; i < 128 * 96; i += 256) {
        int t = i / 96, c = i - t * 96;
        xs[t * 97 + c] += g_xres[(bm + t) * 96 + c];
    }
    // spatial row for each token
    if (tid < 128) {
        int b;
        int sp = decode_spatial((int)bm + tid, b);
        sprow[tid] = b * SP + sp;
    }
    __syncthreads();

    if (tid < 128) {
        const float* row = xs + tid * 97;
        float s = 0.f, ss = 0.f;
        #pragma unroll
        for (int c = 0; c < 96; c++) { float v = row[c]; s += v; ss += v * v; }
        float mean = s * (1.f / 96.f);
        smu[tid] = mean;
        srs[tid] = rsqrtf(ss * (1.f / 96.f) - mean * mean + 1e-5f);
    }
    __syncthreads();

    #pragma unroll
    for (int tk = 0; tk < 16; tk++) {
        int tt = warp * 16 + tk;
        size_t row = (size_t)sprow[tt] * 96;
        float mu = smu[tt], rs = srs[tt];
        #pragma unroll
        for (int rep = 0; rep < 3; rep++) {
            int c = lane + rep * 32;
            float v = xs[tt * 97 + c];
            g_x2[row + c] = v;
            g_hn[row + c] = __float2bfloat16_rn((v - mu) * rs * sg2[c] + sb2[c]);
        }
    }
}

// ============================================================
// K4: fused MLP (M=64): fc1 + GELU in smem, fc2 + residual + transpose out
// ============================================================
#define ML_AS   0
#define ML_BS   13312
#define ML_M1   33280
#define ML_SIZE 86528

__device__ __forceinline__ void mma64(const uint32_t* As, const uint32_t* Bs,
                                      float acc[6][4], int g, int t4, int wm, int wn)
{
    #pragma unroll
    for (int ks = 0; ks < 6; ks++) {
        int k8 = ks * 8;
        uint32_t af[4];
        int rb = wm * 16;
        af[0] = As[(rb + g    ) * 52 + k8 + t4    ];
        af[1] = As[(rb + g + 8) * 52 + k8 + t4    ];
        af[2] = As[(rb + g    ) * 52 + k8 + t4 + 4];
        af[3] = As[(rb + g + 8) * 52 + k8 + t4 + 4];
        uint32_t bf[6][2];
        #pragma unroll
        for (int nt = 0; nt < 6; nt++) {
            int nb = wn * 48 + nt * 8;
            bf[nt][0] = Bs[(nb + g) * 52 + k8 + t4    ];
            bf[nt][1] = Bs[(nb + g) * 52 + k8 + t4 + 4];
        }
        #pragma unroll
        for (int nt = 0; nt < 6; nt++)
            mma_bf16(acc[nt], af, bf[nt]);
    }
}

__global__ void __launch_bounds__(256)
k_mlp(const float* __restrict__ f1bias, const float* __restrict__ f2bias,
      float* __restrict__ out)
{
    extern __shared__ char smem[];
    uint32_t* As   = (uint32_t*)(smem + ML_AS);
    uint32_t* Bs   = (uint32_t*)(smem + ML_BS);
    float*    sout = (float*)(smem + ML_AS);

    int tid = threadIdx.x;
    size_t bm = (size_t)blockIdx.x * 64;
    int warp = tid >> 5, lane = tid & 31, g = lane >> 2, t4 = lane & 3;
    int wm = warp >> 1, wn = warp & 1;

    for (int i = tid; i < 64 * 12; i += 256) {
        int row = i / 12, q = i - row * 12;
        ((uint4*)&As[row * 52])[q] = ((const uint4*)(g_hn + (bm + row) * 96))[q];
    }

    for (int bt = 0; bt < 4; bt++) {
        stage_B96(g_wfc1, bt * 96, Bs, tid);
        __syncthreads();
        float acc[6][4];
        #pragma unroll
        for (int j = 0; j < 6; j++)
            #pragma unroll
            for (int r = 0; r < 4; r++) acc[j][r] = 0.f;
        mma64(As, Bs, acc, g, t4, wm, wn);
        uint32_t* m1 = (uint32_t*)(smem + ML_M1 + bt * 13312);
        #pragma unroll
        for (int nt = 0; nt < 6; nt++) {
            int ncol = wn * 48 + nt * 8 + t4 * 2;
            #pragma unroll
            for (int half = 0; half < 2; half++) {
                int row = wm * 16 + g + half * 8;
                float v0 = acc[nt][half * 2 + 0] + f1bias[bt * 96 + ncol];
                float v1 = acc[nt][half * 2 + 1] + f1bias[bt * 96 + ncol + 1];
                v0 = 0.5f * v0 * (1.f + erff(v0 * 0.70710678118654752f));
                v1 = 0.5f * v1 * (1.f + erff(v1 * 0.70710678118654752f));
                m1[row * 52 + (ncol >> 1)] = packbf(v0, v1);
            }
        }
        __syncthreads();
    }

    float acc2[6][4];
    #pragma unroll
    for (int j = 0; j < 6; j++)
        #pragma unroll
        for (int r = 0; r < 4; r++) acc2[j][r] = 0.f;

    for (int kc = 0; kc < 4; kc++) {
        for (int i = tid; i < 96 * 12; i += 256) {
            int row = i / 12, q = i - row * 12;
            ((uint4*)&Bs[row * 52])[q] =
                ((const uint4*)(g_wfc2 + (size_t)row * 384 + kc * 96))[q];
        }
        __syncthreads();
        const uint32_t* m1 = (const uint32_t*)(smem + ML_M1 + kc * 13312);
        mma64(m1, Bs, acc2, g, t4, wm, wn);
        __syncthreads();
    }

    int b   = (int)(bm >> 17);
    int sp0 = (int)(bm & (SP - 1));

    #pragma unroll
    for (int p = 0; p < 2; p++) {
        if (wn == p) {
            #pragma unroll
            for (int nt = 0; nt < 6; nt++) {
                int cl = nt * 8 + t4 * 2;
                #pragma unroll
                for (int half = 0; half < 2; half++) {
                    int rl = wm * 16 + g + half * 8;
                    float2 xv = *(const float2*)&g_x2[(bm + rl) * 96 + p * 48 + cl];
                    sout[(cl    ) * 68 + rl] = acc2[nt][half * 2 + 0] + f2bias[p * 48 + cl    ] + xv.x;
                    sout[(cl + 1) * 68 + rl] = acc2[nt][half * 2 + 1] + f2bias[p * 48 + cl + 1] + xv.y;
                }
            }
        }
        __syncthreads();
        for (int i = tid; i < 48 * 64; i += 256) {
            int c = i >> 6, tk = i & 63;
            out[((size_t)b * 96 + p * 48 + c) * SP + sp0 + tk] = sout[c * 68 + tk];
        }
        __syncthreads();
    }
}

// ============================================================
// launch
// ============================================================
extern "C" void kernel_launch(void* const* d_in, const int* in_sizes, int n_in,
                              void* d_out, int out_size)
{
    const float* x    = (const float*)d_in[0];
    const float* n1g  = (const float*)d_in[1];
    const float* n1b  = (const float*)d_in[2];
    const float* qkvw = (const float*)d_in[3];
    const float* qkvb = (const float*)d_in[4];
    const float* rpb  = (const float*)d_in[5];
    const float* pw   = (const float*)d_in[6];
    const float* pb   = (const float*)d_in[7];
    const float* n2g  = (const float*)d_in[8];
    const float* n2b  = (const float*)d_in[9];
    const float* f1w  = (const float*)d_in[10];
    const float* f1b  = (const float*)d_in[11];
    const float* f2w  = (const float*)d_in[12];
    const float* f2b  = (const float*)d_in[13];
    float* out = (float*)d_out;

    static int smem_set = 0;
    if (!smem_set) {
        cudaFuncSetAttribute(k_qkv,  cudaFuncAttributeMaxDynamicSharedMemorySize, 47 * 1024);
        cudaFuncSetAttribute(k_attn, cudaFuncAttributeMaxDynamicSharedMemorySize, 56 * 1024);
        cudaFuncSetAttribute(k_proj, cudaFuncAttributeMaxDynamicSharedMemorySize, 52 * 1024);
        cudaFuncSetAttribute(k_mlp,  cudaFuncAttributeMaxDynamicSharedMemorySize, ML_SIZE);
        smem_set = 1;
    }

    const int SZ_GEMM = 46592;
    const int SZ_ATTN = 4 * 64 * 24 * 4 * 2 + 4 * 344 * 4 + 64 * 4;
    const int SZ_PROJ = 51968;

    k_wconv<<<432, 256>>>(qkvw, pw, f1w, f2w);
    k_pre <<<BATCH * DD * HH * 2, 128>>>(x, n1g, n1b);
    k_qkv <<<NTOK / 128, 256, SZ_GEMM>>>(qkvb);
    k_attn<<<BATCH * NWIN, 256, SZ_ATTN>>>(rpb);
    k_proj<<<NTOK / 128, 256, SZ_PROJ>>>(pb, n2g, n2b);
    k_mlp <<<NTOK / 64, 256, ML_SIZE>>>(f1b, f2b, out);
}

// round 7
// speedup vs baseline: 1.3802x; 1.3802x over previous
#include <cuda_runtime.h>
#include <cuda_bf16.h>
#include <math.h>
#include <stdint.h>

// ---------------- problem constants ----------------
#define CDIM   96
#define DD     32
#define HH     64
#define WWD    64
#define BATCH  2
#define SP     131072
#define NTOK   (BATCH * SP)
#define NWIN   2048
#define NHEAD  4
#define HDIM   24
#define NWT    64

// ---------------- device scratch ----------------
__device__ __nv_bfloat16 g_qkv [(size_t)NTOK * 3 * CDIM];  // window-token-major
__device__ __nv_bfloat16 g_att [(size_t)NTOK * CDIM];      // window-token-major
__device__ float         g_x2  [(size_t)NTOK * CDIM];      // residual, SPATIAL token-major
__device__ __nv_bfloat16 g_hn  [(size_t)NTOK * CDIM];      // LN2 out, SPATIAL token-major
__device__ __nv_bfloat16 g_m1  [(size_t)NTOK * 4 * CDIM];  // fc1+gelu, SPATIAL token-major
// bf16 weights
__device__ __nv_bfloat16 g_wqkv[288 * 96];
__device__ __nv_bfloat16 g_wproj[96 * 96];
__device__ __nv_bfloat16 g_wfc1[384 * 96];
__device__ __nv_bfloat16 g_wfc2[96 * 384];

__device__ __forceinline__ uint32_t packbf(float a, float b) {
    __nv_bfloat162 h = __floats2bfloat162_rn(a, b);
    return *reinterpret_cast<uint32_t*>(&h);
}
__device__ __forceinline__ float2 unpackbf(uint32_t u) {
    return __bfloat1622float2(*reinterpret_cast<const __nv_bfloat162*>(&u));
}

// FMA-pipe exp: exp(x) = 2^(x*log2e), 5-term Taylor for 2^f, f in [-0.5,0.5].
// No MUFU. Rel err ~4e-5.
__device__ __forceinline__ float fastexp(float x) {
    float y = x * 1.4426950408889634f;
    float z = y + 12582912.f;                    // round-to-nearest via 2^23+2^22
    int   ni = __float_as_int(z) - 0x4B400000;
    float f = y - (z - 12582912.f);
    float p = fmaf(f, 0.0013333558f, 0.0096181291f);
    p = fmaf(f, p, 0.0555041087f);
    p = fmaf(f, p, 0.2402265070f);
    p = fmaf(f, p, 0.6931471806f);
    p = fmaf(f, p, 1.0f);
    return __int_as_float((ni + 127) << 23) * p;
}

__global__ void k_wconv(const float* __restrict__ a, const float* __restrict__ b,
                        const float* __restrict__ c, const float* __restrict__ d)
{
    int i = blockIdx.x * 256 + threadIdx.x;
    if (i < 27648)            g_wqkv[i]          = __float2bfloat16_rn(a[i]);
    else if (i < 36864)       g_wproj[i - 27648] = __float2bfloat16_rn(b[i - 27648]);
    else if (i < 73728)       g_wfc1[i - 36864]  = __float2bfloat16_rn(c[i - 36864]);
    else if (i < 110592)      g_wfc2[i - 73728]  = __float2bfloat16_rn(d[i - 73728]);
}

// ---------------- mma helpers (M=128, K=96 single-shot, pitch 52 u32) ----------------
#define PITCH 52

__device__ __forceinline__ void mma_bf16(float c[4], const uint32_t a[4], const uint32_t b[2]) {
    asm volatile(
        "mma.sync.aligned.m16n8k16.row.col.f32.bf16.bf16.f32 "
        "{%0,%1,%2,%3}, {%4,%5,%6,%7}, {%8,%9}, {%0,%1,%2,%3};\n"
        : "+f"(c[0]), "+f"(c[1]), "+f"(c[2]), "+f"(c[3])
        : "r"(a[0]), "r"(a[1]), "r"(a[2]), "r"(a[3]), "r"(b[0]), "r"(b[1]));
}

__device__ __forceinline__ void mma_tile96(const uint32_t* As, const uint32_t* Bs,
                                           float acc[2][6][4], int g, int t4, int wm, int wn)
{
    #pragma unroll
    for (int ks = 0; ks < 6; ks++) {
        int k8 = ks * 8;
        uint32_t af[2][4];
        #pragma unroll
        for (int mt = 0; mt < 2; mt++) {
            int rb = wm * 32 + mt * 16;
            af[mt][0] = As[(rb + g    ) * PITCH + k8 + t4    ];
            af[mt][1] = As[(rb + g + 8) * PITCH + k8 + t4    ];
            af[mt][2] = As[(rb + g    ) * PITCH + k8 + t4 + 4];
            af[mt][3] = As[(rb + g + 8) * PITCH + k8 + t4 + 4];
        }
        uint32_t bf[6][2];
        #pragma unroll
        for (int nt = 0; nt < 6; nt++) {
            int nb = wn * 48 + nt * 8;
            bf[nt][0] = Bs[(nb + g) * PITCH + k8 + t4    ];
            bf[nt][1] = Bs[(nb + g) * PITCH + k8 + t4 + 4];
        }
        #pragma unroll
        for (int mt = 0; mt < 2; mt++)
            #pragma unroll
            for (int nt = 0; nt < 6; nt++)
                mma_bf16(acc[mt][nt], af[mt], bf[nt]);
    }
}

__device__ __forceinline__ void stage_A96(const __nv_bfloat16* A, size_t bm, uint32_t* As, int tid) {
    for (int i = tid; i < 128 * 12; i += 256) {
        int row = i / 12, q = i - row * 12;
        ((uint4*)&As[row * PITCH])[q] = ((const uint4*)(A + (bm + row) * 96))[q];
    }
}
__device__ __forceinline__ void stage_B96(const __nv_bfloat16* Wb, int bn, uint32_t* Bs, int tid) {
    for (int i = tid; i < 96 * 12; i += 256) {
        int row = i / 12, q = i - row * 12;
        ((uint4*)&Bs[row * PITCH])[q] = ((const uint4*)(Wb + (size_t)(bn + row) * 96))[q];
    }
}

// decode window-token-major row r -> spatial coords (after un-shift)
__device__ __forceinline__ void decode_tok(int r, int& b, int& d, int& h, int& w) {
    int widx = r >> 6, inner = r & 63;
    b = widx >> 11;
    int wi = widx & 2047;
    int wd = wi >> 8, wh = (wi >> 4) & 15, ww = wi & 15;
    int id = inner >> 4, ih = (inner >> 2) & 3, iw = inner & 3;
    d = (wd * 4 + id + 2) & 31;
    h = (wh * 4 + ih + 2) & 63;
    w = (ww * 4 + iw + 2) & 63;
}

// ============================================================
// K1: fused LN1 + roll + window + qkv GEMM (3 N-tiles in-block)
// ============================================================
__global__ void __launch_bounds__(256)
k_qkv(const float* __restrict__ x, const float* __restrict__ gw,
      const float* __restrict__ gb, const float* __restrict__ qbias)
{
    extern __shared__ char smem[];
    uint32_t* As = (uint32_t*)smem;                // 26624B
    uint32_t* Bs = (uint32_t*)(smem + 26624);      // 19968B
    float* sgw = (float*)(smem + 46592);
    float* sgb = sgw + 96;

    int tid = threadIdx.x;
    if (tid < 96) { sgw[tid] = gw[tid]; sgb[tid] = gb[tid]; }

    size_t bm = (size_t)blockIdx.x * 128;
    int t = tid & 127;
    int b, d, h, w;
    decode_tok((int)bm + t, b, d, h, w);
    size_t xbase = ((size_t)b * 96) * SP + (size_t)d * 4096 + h * 64 + w;
    int c0 = tid >> 7;   // 0 or 1

    for (int p = c0; p < 48; p += 2) {
        float v0 = x[xbase + (size_t)(2 * p) * SP];
        float v1 = x[xbase + (size_t)(2 * p + 1) * SP];
        As[t * PITCH + p] = packbf(v0, v1);
    }
    __syncthreads();

    if (tid < 128) {
        uint32_t* row = As + tid * PITCH;
        float s = 0.f, ss = 0.f;
        #pragma unroll
        for (int p = 0; p < 48; p++) {
            float2 f = unpackbf(row[p]);
            s += f.x + f.y; ss += f.x * f.x + f.y * f.y;
        }
        float mean = s * (1.f / 96.f);
        float rstd = rsqrtf(ss * (1.f / 96.f) - mean * mean + 1e-5f);
        #pragma unroll
        for (int p = 0; p < 48; p++) {
            float2 f = unpackbf(row[p]);
            f.x = (f.x - mean) * rstd * sgw[2 * p] + sgb[2 * p];
            f.y = (f.y - mean) * rstd * sgw[2 * p + 1] + sgb[2 * p + 1];
            row[p] = packbf(f.x, f.y);
        }
    }
    __syncthreads();

    int warp = tid >> 5, lane = tid & 31, g = lane >> 2, t4 = lane & 3;
    int wm = warp >> 1, wn = warp & 1;

    for (int bt = 0; bt < 3; bt++) {
        stage_B96(g_wqkv, bt * 96, Bs, tid);
        __syncthreads();
        float acc[2][6][4];
        #pragma unroll
        for (int i = 0; i < 2; i++)
            #pragma unroll
            for (int j = 0; j < 6; j++)
                #pragma unroll
                for (int r = 0; r < 4; r++) acc[i][j][r] = 0.f;
        mma_tile96(As, Bs, acc, g, t4, wm, wn);
        #pragma unroll
        for (int mt = 0; mt < 2; mt++)
            #pragma unroll
            for (int nt = 0; nt < 6; nt++) {
                int ncol = wn * 48 + nt * 8 + t4 * 2;
                #pragma unroll
                for (int half = 0; half < 2; half++) {
                    size_t row = bm + wm * 32 + mt * 16 + g + half * 8;
                    float v0 = acc[mt][nt][half * 2 + 0] + qbias[bt * 96 + ncol];
                    float v1 = acc[mt][nt][half * 2 + 1] + qbias[bt * 96 + ncol + 1];
                    *(uint32_t*)&g_qkv[row * 288 + bt * 96 + ncol] = packbf(v0, v1);
                }
            }
        __syncthreads();
    }
}

// ============================================================
// K2: windowed attention, f32 K/V in smem, FMA-pipe exp.
// ============================================================
__global__ void __launch_bounds__(256)
k_attn(const float* __restrict__ rpb)
{
    extern __shared__ char smem[];
    float* kk   = (float*)smem;
    float* vv   = kk + 4 * 64 * 24;
    float* bcol = vv + 4 * 64 * 24;
    int*   gtok = (int*)(bcol + 4 * 344);

    int bn  = blockIdx.x;
    int tid = threadIdx.x;
    int hh  = tid >> 6;
    int tok = tid & 63;

    const uint32_t* qkvb = (const uint32_t*)(g_qkv + (size_t)bn * NWT * 288);

    for (int i = tid; i < 4 * 64 * 12; i += 256) {
        int hph = i / 768;
        int rem = i - hph * 768;
        int j = rem / 12, p = rem - j * 12;
        const uint32_t* base = qkvb + j * 144;
        float2 kf = unpackbf(base[48 + hph * 12 + p]);
        float2 vf = unpackbf(base[96 + hph * 12 + p]);
        kk[(hph * 64 + j) * 24 + 2 * p    ] = kf.x;
        kk[(hph * 64 + j) * 24 + 2 * p + 1] = kf.y;
        vv[(hph * 64 + j) * 24 + 2 * p    ] = vf.x;
        vv[(hph * 64 + j) * 24 + 2 * p + 1] = vf.y;
    }
    for (int i = tid; i < 4 * 343; i += 256) {
        int hph = i / 343, r = i - hph * 343;
        bcol[hph * 344 + r] = rpb[r * NHEAD + hph];
    }
    if (tid < NWT) {
        int widx = bn & (NWIN - 1);
        int wd = widx >> 8, wh = (widx >> 4) & 15, ww = widx & 15;
        int id = tid >> 4, ih = (tid >> 2) & 3, iw = tid & 3;
        int da = wd * 4 + id, ha = wh * 4 + ih, wa = ww * 4 + iw;
        int rd = (da < DD  - 4) ? 0 : ((da < DD  - 2) ? 1 : 2);
        int rh = (ha < HH  - 4) ? 0 : ((ha < HH  - 2) ? 1 : 2);
        int rw = (wa < WWD - 4) ? 0 : ((wa < WWD - 2) ? 1 : 2);
        gtok[tid] = rd * 9 + rh * 3 + rw;
    }

    float q[HDIM];
    {
        const uint32_t* base = qkvb + tok * 144;
        #pragma unroll
        for (int p = 0; p < 12; p++) {
            float2 f = unpackbf(base[hh * 12 + p]);
            q[2 * p    ] = f.x * 0.2041241452319315f;
            q[2 * p + 1] = f.y * 0.2041241452319315f;
        }
    }
    __syncthreads();

    int id = tok >> 4, ih = (tok >> 2) & 3, iw = tok & 3;
    int relbase = (id + 3) * 49 + (ih + 3) * 7 + (iw + 3);
    int mygrp = gtok[tok];
    const float* bch = bcol + hh * 344;
    const float4* kf4 = (const float4*)(kk + hh * 64 * 24);
    const float4* vf4 = (const float4*)(vv + hh * 64 * 24);

    float o[HDIM];
    #pragma unroll
    for (int dd = 0; dd < HDIM; dd++) o[dd] = 0.f;
    float sum = 0.f;

    #pragma unroll 8
    for (int j = 0; j < NWT; j++) {
        const float4* kr = kf4 + j * 6;
        float a0 = 0.f, a1 = 0.f;
        #pragma unroll
        for (int p = 0; p < 3; p++) {
            float4 kva = kr[p];
            float4 kvb = kr[p + 3];
            a0 = fmaf(q[4 * p     ], kva.x, a0);
            a0 = fmaf(q[4 * p + 1 ], kva.y, a0);
            a0 = fmaf(q[4 * p + 2 ], kva.z, a0);
            a0 = fmaf(q[4 * p + 3 ], kva.w, a0);
            a1 = fmaf(q[4 * p + 12], kvb.x, a1);
            a1 = fmaf(q[4 * p + 13], kvb.y, a1);
            a1 = fmaf(q[4 * p + 14], kvb.z, a1);
            a1 = fmaf(q[4 * p + 15], kvb.w, a1);
        }
        int jcode = (j >> 4) * 49 + ((j >> 2) & 3) * 7 + (j & 3);
        float a = a0 + a1 + bch[relbase - jcode];
        float e = (gtok[j] == mygrp) ? fastexp(a) : 0.f;
        sum += e;
        const float4* vr = vf4 + j * 6;
        #pragma unroll
        for (int p = 0; p < 6; p++) {
            float4 vvec = vr[p];
            o[4 * p    ] = fmaf(e, vvec.x, o[4 * p    ]);
            o[4 * p + 1] = fmaf(e, vvec.y, o[4 * p + 1]);
            o[4 * p + 2] = fmaf(e, vvec.z, o[4 * p + 2]);
            o[4 * p + 3] = fmaf(e, vvec.w, o[4 * p + 3]);
        }
    }
    float inv = 1.f / sum;

    uint32_t* op = (uint32_t*)(g_att + ((size_t)bn * NWT + tok) * CDIM + hh * HDIM);
    #pragma unroll
    for (int p = 0; p < 12; p++)
        op[p] = packbf(o[2 * p] * inv, o[2 * p + 1] * inv);
}

// ============================================================
// K3: proj GEMM + window reverse + roll + residual + LN2
// ============================================================
__global__ void __launch_bounds__(256)
k_proj(const float* __restrict__ x, const float* __restrict__ pbias,
       const float* __restrict__ g2, const float* __restrict__ b2)
{
    extern __shared__ char smem[];
    uint32_t* As = (uint32_t*)smem;
    uint32_t* Bs = (uint32_t*)(smem + 26624);
    float* xs    = (float*)smem;                  // [128][97]
    int*   sprow = (int*)(smem + 49664);
    float* smu   = (float*)(smem + 50176);
    float* srs   = (float*)(smem + 50688);
    float* sg2   = (float*)(smem + 51200);
    float* sb2   = (float*)(smem + 51584);

    int tid = threadIdx.x;
    if (tid < 96) { sg2[tid] = g2[tid]; sb2[tid] = b2[tid]; }

    size_t bm = (size_t)blockIdx.x * 128;
    stage_A96(g_att, bm, As, tid);
    stage_B96(g_wproj, 0, Bs, tid);
    __syncthreads();

    int warp = tid >> 5, lane = tid & 31, g = lane >> 2, t4 = lane & 3;
    int wm = warp >> 1, wn = warp & 1;

    float acc[2][6][4];
    #pragma unroll
    for (int i = 0; i < 2; i++)
        #pragma unroll
        for (int j = 0; j < 6; j++)
            #pragma unroll
            for (int r = 0; r < 4; r++) acc[i][j][r] = 0.f;
    mma_tile96(As, Bs, acc, g, t4, wm, wn);
    __syncthreads();

    #pragma unroll
    for (int mt = 0; mt < 2; mt++)
        #pragma unroll
        for (int nt = 0; nt < 6; nt++) {
            int cl = wn * 48 + nt * 8 + t4 * 2;
            #pragma unroll
            for (int half = 0; half < 2; half++) {
                int rl = wm * 32 + mt * 16 + g + half * 8;
                xs[rl * 97 + cl    ] = acc[mt][nt][half * 2 + 0] + pbias[cl];
                xs[rl * 97 + cl + 1] = acc[mt][nt][half * 2 + 1] + pbias[cl + 1];
            }
        }
    __syncthreads();

    int t = tid & 127;
    int b, d, h, w;
    decode_tok((int)bm + t, b, d, h, w);
    int spoff = d * 4096 + h * 64 + w;
    size_t xbase = ((size_t)b * 96) * SP + spoff;
    if (tid < 128) sprow[tid] = b * SP + spoff;
    int c0 = tid >> 7;
    for (int c = c0; c < 96; c += 2)
        xs[t * 97 + c] += x[xbase + (size_t)c * SP];
    __syncthreads();

    if (tid < 128) {
        const float* row = xs + tid * 97;
        float s = 0.f, ss = 0.f;
        #pragma unroll
        for (int c = 0; c < 96; c++) { float v = row[c]; s += v; ss += v * v; }
        float mean = s * (1.f / 96.f);
        smu[tid] = mean;
        srs[tid] = rsqrtf(ss * (1.f / 96.f) - mean * mean + 1e-5f);
    }
    __syncthreads();

    #pragma unroll
    for (int tk = 0; tk < 16; tk++) {
        int tt = warp * 16 + tk;
        size_t row = (size_t)sprow[tt] * 96;
        float mu = smu[tt], rs = srs[tt];
        #pragma unroll
        for (int rep = 0; rep < 3; rep++) {
            int c = lane + rep * 32;
            float v = xs[tt * 97 + c];
            g_x2[row + c] = v;
            g_hn[row + c] = __float2bfloat16_rn((v - mu) * rs * sg2[c] + sb2[c]);
        }
    }
}

// ============================================================
// K4: fc1 GEMM + GELU (4 N-tiles in-block, M=128)
// ============================================================
__global__ void __launch_bounds__(256)
k_fc1(const float* __restrict__ f1bias)
{
    extern __shared__ char smem[];
    uint32_t* As = (uint32_t*)smem;
    uint32_t* Bs = (uint32_t*)(smem + 26624);

    int tid = threadIdx.x;
    size_t bm = (size_t)blockIdx.x * 128;
    stage_A96(g_hn, bm, As, tid);

    int warp = tid >> 5, lane = tid & 31, g = lane >> 2, t4 = lane & 3;
    int wm = warp >> 1, wn = warp & 1;

    for (int bt = 0; bt < 4; bt++) {
        if (bt) __syncthreads();
        stage_B96(g_wfc1, bt * 96, Bs, tid);
        __syncthreads();
        float acc[2][6][4];
        #pragma unroll
        for (int i = 0; i < 2; i++)
            #pragma unroll
            for (int j = 0; j < 6; j++)
                #pragma unroll
                for (int r = 0; r < 4; r++) acc[i][j][r] = 0.f;
        mma_tile96(As, Bs, acc, g, t4, wm, wn);
        #pragma unroll
        for (int mt = 0; mt < 2; mt++)
            #pragma unroll
            for (int nt = 0; nt < 6; nt++) {
                int ncol = wn * 48 + nt * 8 + t4 * 2;
                #pragma unroll
                for (int half = 0; half < 2; half++) {
                    size_t row = bm + wm * 32 + mt * 16 + g + half * 8;
                    float v0 = acc[mt][nt][half * 2 + 0] + f1bias[bt * 96 + ncol];
                    float v1 = acc[mt][nt][half * 2 + 1] + f1bias[bt * 96 + ncol + 1];
                    v0 = 0.5f * v0 * (1.f + erff(v0 * 0.70710678118654752f));
                    v1 = 0.5f * v1 * (1.f + erff(v1 * 0.70710678118654752f));
                    *(uint32_t*)&g_m1[row * 384 + bt * 96 + ncol] = packbf(v0, v1);
                }
            }
    }
}

// ============================================================
// K5: fc2 GEMM (K=384) + residual + transpose to out (M=128)
// ============================================================
__global__ void __launch_bounds__(256)
k_fc2(const float* __restrict__ f2bias, float* __restrict__ out)
{
    extern __shared__ char smem[];
    uint32_t* As = (uint32_t*)smem;
    uint32_t* Bs = (uint32_t*)(smem + 26624);
    float* sout  = (float*)smem;

    int tid = threadIdx.x;
    size_t bm = (size_t)blockIdx.x * 128;
    int warp = tid >> 5, lane = tid & 31, g = lane >> 2, t4 = lane & 3;
    int wm = warp >> 1, wn = warp & 1;

    float acc[2][6][4];
    #pragma unroll
    for (int i = 0; i < 2; i++)
        #pragma unroll
        for (int j = 0; j < 6; j++)
            #pragma unroll
            for (int r = 0; r < 4; r++) acc[i][j][r] = 0.f;

    for (int kc = 0; kc < 4; kc++) {
        if (kc) __syncthreads();
        int k0 = kc * 96;
        for (int i = tid; i < 128 * 12; i += 256) {
            int row = i / 12, q = i - row * 12;
            ((uint4*)&As[row * PITCH])[q] = ((const uint4*)(g_m1 + (bm + row) * 384 + k0))[q];
        }
        for (int i = tid; i < 96 * 12; i += 256) {
            int row = i / 12, q = i - row * 12;
            ((uint4*)&Bs[row * PITCH])[q] = ((const uint4*)(g_wfc2 + (size_t)row * 384 + k0))[q];
        }
        __syncthreads();
        mma_tile96(As, Bs, acc, g, t4, wm, wn);
    }
    __syncthreads();

    int b   = (int)(bm >> 17);
    int sp0 = (int)(bm & (SP - 1));

    #pragma unroll
    for (int p = 0; p < 2; p++) {
        if (wn == p) {
            #pragma unroll
            for (int mt = 0; mt < 2; mt++)
                #pragma unroll
                for (int nt = 0; nt < 6; nt++) {
                    int cl = nt * 8 + t4 * 2;
                    #pragma unroll
                    for (int half = 0; half < 2; half++) {
                        int rl = wm * 32 + mt * 16 + g + half * 8;
                        float2 xv = *(const float2*)&g_x2[(bm + rl) * 96 + p * 48 + cl];
                        sout[(cl    ) * 132 + rl] = acc[mt][nt][half * 2 + 0] + f2bias[p * 48 + cl    ] + xv.x;
                        sout[(cl + 1) * 132 + rl] = acc[mt][nt][half * 2 + 1] + f2bias[p * 48 + cl + 1] + xv.y;
                    }
                }
        }
        __syncthreads();
        for (int i = tid; i < 48 * 128; i += 256) {
            int c = i >> 7, tk = i & 127;
            out[((size_t)b * 96 + p * 48 + c) * SP + sp0 + tk] = sout[c * 132 + tk];
        }
        __syncthreads();
    }
}

// ============================================================
// launch
// ============================================================
extern "C" void kernel_launch(void* const* d_in, const int* in_sizes, int n_in,
                              void* d_out, int out_size)
{
    const float* x    = (const float*)d_in[0];
    const float* n1g  = (const float*)d_in[1];
    const float* n1b  = (const float*)d_in[2];
    const float* qkvw = (const float*)d_in[3];
    const float* qkvb = (const float*)d_in[4];
    const float* rpb  = (const float*)d_in[5];
    const float* pw   = (const float*)d_in[6];
    const float* pb   = (const float*)d_in[7];
    const float* n2g  = (const float*)d_in[8];
    const float* n2b  = (const float*)d_in[9];
    const float* f1w  = (const float*)d_in[10];
    const float* f1b  = (const float*)d_in[11];
    const float* f2w  = (const float*)d_in[12];
    const float* f2b  = (const float*)d_in[13];
    float* out = (float*)d_out;

    static int smem_set = 0;
    if (!smem_set) {
        cudaFuncSetAttribute(k_qkv,  cudaFuncAttributeMaxDynamicSharedMemorySize, 48 * 1024);
        cudaFuncSetAttribute(k_attn, cudaFuncAttributeMaxDynamicSharedMemorySize, 56 * 1024);
        cudaFuncSetAttribute(k_proj, cudaFuncAttributeMaxDynamicSharedMemorySize, 52 * 1024);
        cudaFuncSetAttribute(k_fc1,  cudaFuncAttributeMaxDynamicSharedMemorySize, 47 * 1024);
        cudaFuncSetAttribute(k_fc2,  cudaFuncAttributeMaxDynamicSharedMemorySize, 47 * 1024);
        smem_set = 1;
    }

    const int SZ_QKV  = 46592 + 768;
    const int SZ_ATTN = 4 * 64 * 24 * 4 * 2 + 4 * 344 * 4 + 64 * 4;
    const int SZ_PROJ = 51968;
    const int SZ_GEMM = 46592;

    k_wconv<<<432, 256>>>(qkvw, pw, f1w, f2w);
    k_qkv <<<NTOK / 128, 256, SZ_QKV >>>(x, n1g, n1b, qkvb);
    k_attn<<<BATCH * NWIN, 256, SZ_ATTN>>>(rpb);
    k_proj<<<NTOK / 128, 256, SZ_PROJ>>>(x, pb, n2g, n2b);
    k_fc1 <<<NTOK / 128, 256, SZ_GEMM>>>(f1b);
    k_fc2 <<<NTOK / 128, 256, SZ_GEMM>>>(f2b, out);
}

// round 8
// speedup vs baseline: 1.7358x; 1.2576x over previous
#include <cuda_runtime.h>
#include <cuda_bf16.h>
#include <math.h>
#include <stdint.h>

// ---------------- problem constants ----------------
#define CDIM   96
#define DD     32
#define HH     64
#define WWD    64
#define BATCH  2
#define SP     131072
#define NTOK   (BATCH * SP)
#define NWIN   2048
#define NHEAD  4
#define HDIM   24
#define NWT    64

// ---------------- device scratch ----------------
__device__ __nv_bfloat16 g_qkv [(size_t)NTOK * 3 * CDIM];  // window-token-major (q pre-scaled)
__device__ __nv_bfloat16 g_att [(size_t)NTOK * CDIM];      // window-token-major
__device__ float         g_x2  [(size_t)NTOK * CDIM];      // residual, SPATIAL token-major
__device__ __nv_bfloat16 g_hn  [(size_t)NTOK * CDIM];      // LN2 out, SPATIAL token-major
__device__ __nv_bfloat16 g_m1  [(size_t)NTOK * 4 * CDIM];  // fc1+gelu
__device__ uint32_t      g_biasF[8192];                    // fragment-ordered bias table
// bf16 weights
__device__ __nv_bfloat16 g_wqkv[288 * 96];
__device__ __nv_bfloat16 g_wproj[96 * 96];
__device__ __nv_bfloat16 g_wfc1[384 * 96];
__device__ __nv_bfloat16 g_wfc2[96 * 384];

__device__ __forceinline__ uint32_t packbf(float a, float b) {
    __nv_bfloat162 h = __floats2bfloat162_rn(a, b);
    return *reinterpret_cast<uint32_t*>(&h);
}
__device__ __forceinline__ float2 unpackbf(uint32_t u) {
    return __bfloat1622float2(*reinterpret_cast<const __nv_bfloat162*>(&u));
}

__global__ void k_wconv(const float* __restrict__ a, const float* __restrict__ b,
                        const float* __restrict__ c, const float* __restrict__ d)
{
    int i = blockIdx.x * 256 + threadIdx.x;
    if (i < 27648)            g_wqkv[i]          = __float2bfloat16_rn(a[i]);
    else if (i < 36864)       g_wproj[i - 27648] = __float2bfloat16_rn(b[i - 27648]);
    else if (i < 73728)       g_wfc1[i - 36864]  = __float2bfloat16_rn(c[i - 36864]);
    else if (i < 110592)      g_wfc2[i - 73728]  = __float2bfloat16_rn(d[i - 73728]);
}

// Precompute rel-pos bias table in mma-fragment order:
// addr = ((h*8 + (r>>4)*2 + ((r>>3)&1))*8 + nt)*32 + (r&7)*4 + t4
// value = packbf(bias(h,r,8nt+2t4), bias(h,r,8nt+2t4+1))
__global__ void k_bias(const float* __restrict__ rpb)
{
    int idx = blockIdx.x * 256 + threadIdx.x;   // 8192
    int t4 = idx & 3;
    int nt = (idx >> 2) & 7;
    int r  = (idx >> 5) & 63;
    int h  = idx >> 11;
    int j0 = nt * 8 + t4 * 2;
    int id = r >> 4, ih = (r >> 2) & 3, iw = r & 3;
    auto relf = [&](int j) {
        int jd = j >> 4, jh = (j >> 2) & 3, jw = j & 3;
        return (id - jd + 3) * 49 + (ih - jh + 3) * 7 + (iw - jw + 3);
    };
    float b0 = rpb[relf(j0) * NHEAD + h];
    float b1 = rpb[relf(j0 + 1) * NHEAD + h];
    uint32_t addr = (uint32_t)(((h * 8 + (r >> 4) * 2 + ((r >> 3) & 1)) * 8 + nt) * 32
                               + (r & 7) * 4 + t4);
    g_biasF[addr] = packbf(b0, b1);
}

// ---------------- mma helpers ----------------
#define PITCH 52

__device__ __forceinline__ void mma_bf16(float c[4], const uint32_t a[4], const uint32_t b[2]) {
    asm volatile(
        "mma.sync.aligned.m16n8k16.row.col.f32.bf16.bf16.f32 "
        "{%0,%1,%2,%3}, {%4,%5,%6,%7}, {%8,%9}, {%0,%1,%2,%3};\n"
        : "+f"(c[0]), "+f"(c[1]), "+f"(c[2]), "+f"(c[3])
        : "r"(a[0]), "r"(a[1]), "r"(a[2]), "r"(a[3]), "r"(b[0]), "r"(b[1]));
}

__device__ __forceinline__ void mma_tile96(const uint32_t* As, const uint32_t* Bs,
                                           float acc[2][6][4], int g, int t4, int wm, int wn)
{
    #pragma unroll
    for (int ks = 0; ks < 6; ks++) {
        int k8 = ks * 8;
        uint32_t af[2][4];
        #pragma unroll
        for (int mt = 0; mt < 2; mt++) {
            int rb = wm * 32 + mt * 16;
            af[mt][0] = As[(rb + g    ) * PITCH + k8 + t4    ];
            af[mt][1] = As[(rb + g + 8) * PITCH + k8 + t4    ];
            af[mt][2] = As[(rb + g    ) * PITCH + k8 + t4 + 4];
            af[mt][3] = As[(rb + g + 8) * PITCH + k8 + t4 + 4];
        }
        uint32_t bf[6][2];
        #pragma unroll
        for (int nt = 0; nt < 6; nt++) {
            int nb = wn * 48 + nt * 8;
            bf[nt][0] = Bs[(nb + g) * PITCH + k8 + t4    ];
            bf[nt][1] = Bs[(nb + g) * PITCH + k8 + t4 + 4];
        }
        #pragma unroll
        for (int mt = 0; mt < 2; mt++)
            #pragma unroll
            for (int nt = 0; nt < 6; nt++)
                mma_bf16(acc[mt][nt], af[mt], bf[nt]);
    }
}

__device__ __forceinline__ void stage_A96(const __nv_bfloat16* A, size_t bm, uint32_t* As, int tid) {
    for (int i = tid; i < 128 * 12; i += 256) {
        int row = i / 12, q = i - row * 12;
        ((uint4*)&As[row * PITCH])[q] = ((const uint4*)(A + (bm + row) * 96))[q];
    }
}
__device__ __forceinline__ void stage_B96(const __nv_bfloat16* Wb, int bn, uint32_t* Bs, int tid) {
    for (int i = tid; i < 96 * 12; i += 256) {
        int row = i / 12, q = i - row * 12;
        ((uint4*)&Bs[row * PITCH])[q] = ((const uint4*)(Wb + (size_t)(bn + row) * 96))[q];
    }
}

__device__ __forceinline__ void decode_tok(int r, int& b, int& d, int& h, int& w) {
    int widx = r >> 6, inner = r & 63;
    b = widx >> 11;
    int wi = widx & 2047;
    int wd = wi >> 8, wh = (wi >> 4) & 15, ww = wi & 15;
    int id = inner >> 4, ih = (inner >> 2) & 3, iw = inner & 3;
    d = (wd * 4 + id + 2) & 31;
    h = (wh * 4 + ih + 2) & 63;
    w = (ww * 4 + iw + 2) & 63;
}

// ============================================================
// K1: fused LN1 + roll + window + qkv GEMM. q output pre-scaled by 24^-0.5.
// ============================================================
__global__ void __launch_bounds__(256)
k_qkv(const float* __restrict__ x, const float* __restrict__ gw,
      const float* __restrict__ gb, const float* __restrict__ qbias)
{
    extern __shared__ char smem[];
    uint32_t* As = (uint32_t*)smem;
    uint32_t* Bs = (uint32_t*)(smem + 26624);
    float* sgw = (float*)(smem + 46592);
    float* sgb = sgw + 96;

    int tid = threadIdx.x;
    if (tid < 96) { sgw[tid] = gw[tid]; sgb[tid] = gb[tid]; }

    size_t bm = (size_t)blockIdx.x * 128;
    int t = tid & 127;
    int b, d, h, w;
    decode_tok((int)bm + t, b, d, h, w);
    size_t xbase = ((size_t)b * 96) * SP + (size_t)d * 4096 + h * 64 + w;
    int c0 = tid >> 7;

    for (int p = c0; p < 48; p += 2) {
        float v0 = x[xbase + (size_t)(2 * p) * SP];
        float v1 = x[xbase + (size_t)(2 * p + 1) * SP];
        As[t * PITCH + p] = packbf(v0, v1);
    }
    __syncthreads();

    if (tid < 128) {
        uint32_t* row = As + tid * PITCH;
        float s = 0.f, ss = 0.f;
        #pragma unroll
        for (int p = 0; p < 48; p++) {
            float2 f = unpackbf(row[p]);
            s += f.x + f.y; ss += f.x * f.x + f.y * f.y;
        }
        float mean = s * (1.f / 96.f);
        float rstd = rsqrtf(ss * (1.f / 96.f) - mean * mean + 1e-5f);
        #pragma unroll
        for (int p = 0; p < 48; p++) {
            float2 f = unpackbf(row[p]);
            f.x = (f.x - mean) * rstd * sgw[2 * p] + sgb[2 * p];
            f.y = (f.y - mean) * rstd * sgw[2 * p + 1] + sgb[2 * p + 1];
            row[p] = packbf(f.x, f.y);
        }
    }
    __syncthreads();

    int warp = tid >> 5, lane = tid & 31, g = lane >> 2, t4 = lane & 3;
    int wm = warp >> 1, wn = warp & 1;

    for (int bt = 0; bt < 3; bt++) {
        stage_B96(g_wqkv, bt * 96, Bs, tid);
        __syncthreads();
        float acc[2][6][4];
        #pragma unroll
        for (int i = 0; i < 2; i++)
            #pragma unroll
            for (int j = 0; j < 6; j++)
                #pragma unroll
                for (int r = 0; r < 4; r++) acc[i][j][r] = 0.f;
        mma_tile96(As, Bs, acc, g, t4, wm, wn);
        float scale = (bt == 0) ? 0.2041241452319315f : 1.0f;
        #pragma unroll
        for (int mt = 0; mt < 2; mt++)
            #pragma unroll
            for (int nt = 0; nt < 6; nt++) {
                int ncol = wn * 48 + nt * 8 + t4 * 2;
                #pragma unroll
                for (int half = 0; half < 2; half++) {
                    size_t row = bm + wm * 32 + mt * 16 + g + half * 8;
                    float v0 = (acc[mt][nt][half * 2 + 0] + qbias[bt * 96 + ncol]) * scale;
                    float v1 = (acc[mt][nt][half * 2 + 1] + qbias[bt * 96 + ncol + 1]) * scale;
                    *(uint32_t*)&g_qkv[row * 288 + bt * 96 + ncol] = packbf(v0, v1);
                }
            }
        __syncthreads();
    }
}

// ============================================================
// K2: tensor-core windowed attention. 512 thr = 16 warps:
// warp w -> head w>>2, row slab (w&3)*16. S=Q@K^T via mma,
// softmax in fragments, PV via mma (S frags -> A frags directly).
// ============================================================
// smem u32 offsets
#define AT_QS   0
#define AT_KS   5120
#define AT_VT   10240        // bf16 view, 4*24 rows * 36 u32 pitch
#define AT_BF   13696
#define AT_GT   21888
#define AT_SIZE (21952 * 4)  // 87808 B

__global__ void __launch_bounds__(512)
k_attn()
{
    extern __shared__ uint32_t sm[];
    uint32_t* Qs = sm + AT_QS;
    uint32_t* Ks = sm + AT_KS;
    uint32_t* VtU = sm + AT_VT;
    __nv_bfloat16* Vt = (__nv_bfloat16*)(sm + AT_VT);
    uint32_t* bF = sm + AT_BF;
    int* gtk = (int*)(sm + AT_GT);

    int tid = threadIdx.x;
    int bn  = blockIdx.x;
    int wi  = bn & (NWIN - 1);
    int wd = wi >> 8, wh = (wi >> 4) & 15, ww = wi & 15;
    bool interior = (wd != 7) && (wh != 15) && (ww != 15);

    const uint4* src4 = (const uint4*)(g_qkv + (size_t)bn * NWT * 288);
    const uint32_t* srcU = (const uint32_t*)src4;

    // Q/K staging: 1536 uint4 (sec,h,r,q)
    for (int i = tid; i < 1536; i += 512) {
        int sec = i >> 9;               // 0=q, 1=k  (768 each)
        int rem = i & 511;              // careful: 768 per sec -> use explicit
        // recompute with real split
        sec = i / 768; rem = i - sec * 768;
        int h = rem / 192;
        int r2 = rem - h * 192;
        int r = r2 / 3, q = r2 - r * 3;
        uint4 v = src4[r * 36 + sec * 12 + h * 3 + q];
        uint32_t* dst = (sec ? Ks : Qs) + (h * 64 + r) * 20 + q * 4;
        *(uint4*)dst = v;
    }
    // zero pad cols 12..15 of Q/K rows
    for (int i = tid; i < 512; i += 512) {
        int sec = i >> 8, hr = i & 255;
        uint32_t* dst = (sec ? Ks : Qs) + hr * 20 + 12;
        *(uint4*)dst = make_uint4(0, 0, 0, 0);
    }
    // V transpose: (h, j, p) -> Vt[(h*24+2p)(+1)][j]
    for (int i = tid; i < 3072; i += 512) {
        int h = i / 768;
        int rem = i - h * 768;
        int j = rem / 12, p = rem - j * 12;
        uint32_t v = srcU[j * 144 + 96 + h * 12 + p];
        __nv_bfloat162 bv = *reinterpret_cast<__nv_bfloat162*>(&v);
        Vt[(h * 24 + 2 * p    ) * 72 + j] = bv.x;
        Vt[(h * 24 + 2 * p + 1) * 72 + j] = bv.y;
    }
    // bias table
    {
        const uint4* gb4 = (const uint4*)g_biasF;
        uint4* sb4 = (uint4*)bF;
        for (int i = tid; i < 2048; i += 512) sb4[i] = gb4[i];
    }
    // group ids
    if (tid < 64) {
        int id = tid >> 4, ih = (tid >> 2) & 3, iw = tid & 3;
        int da = wd * 4 + id, ha = wh * 4 + ih, wa = ww * 4 + iw;
        int rd = (da < DD  - 4) ? 0 : ((da < DD  - 2) ? 1 : 2);
        int rh = (ha < HH  - 4) ? 0 : ((ha < HH  - 2) ? 1 : 2);
        int rw = (wa < WWD - 4) ? 0 : ((wa < WWD - 2) ? 1 : 2);
        gtk[tid] = rd * 9 + rh * 3 + rw;
    }
    __syncthreads();

    int w = tid >> 5, lane = tid & 31;
    int g = lane >> 2, t4 = lane & 3;
    int h  = w >> 2;          // head
    int rq = w & 3;           // 16-row slab
    const uint32_t* Qh = Qs + h * 1280;
    const uint32_t* Kh = Ks + h * 1280;

    // ---- S = Q @ K^T  (m16 x n64, k=32 padded)
    float acc[8][4];
    #pragma unroll
    for (int nt = 0; nt < 8; nt++)
        #pragma unroll
        for (int r = 0; r < 4; r++) acc[nt][r] = 0.f;

    #pragma unroll
    for (int ks = 0; ks < 2; ks++) {
        uint32_t a[4];
        a[0] = Qh[(rq * 16 + g    ) * 20 + ks * 8 + t4    ];
        a[1] = Qh[(rq * 16 + g + 8) * 20 + ks * 8 + t4    ];
        a[2] = Qh[(rq * 16 + g    ) * 20 + ks * 8 + t4 + 4];
        a[3] = Qh[(rq * 16 + g + 8) * 20 + ks * 8 + t4 + 4];
        #pragma unroll
        for (int nt = 0; nt < 8; nt++) {
            uint32_t b[2];
            b[0] = Kh[(nt * 8 + g) * 20 + ks * 8 + t4    ];
            b[1] = Kh[(nt * 8 + g) * 20 + ks * 8 + t4 + 4];
            mma_bf16(acc[nt], a, b);
        }
    }

    // ---- softmax in fragments (unnormalized)
    int r0 = rq * 16 + g;
    int r1 = r0 + 8;
    float sum0 = 0.f, sum1 = 0.f;
    int base0 = ((h * 8 + rq * 2 + 0) * 8) * 32 + lane;
    int base1 = ((h * 8 + rq * 2 + 1) * 8) * 32 + lane;

    if (interior) {
        #pragma unroll
        for (int nt = 0; nt < 8; nt++) {
            float2 f0 = unpackbf(bF[base0 + nt * 32]);
            float2 f1 = unpackbf(bF[base1 + nt * 32]);
            float e0 = __expf(acc[nt][0] + f0.x);
            float e1 = __expf(acc[nt][1] + f0.y);
            float e2 = __expf(acc[nt][2] + f1.x);
            float e3 = __expf(acc[nt][3] + f1.y);
            acc[nt][0] = e0; acc[nt][1] = e1; acc[nt][2] = e2; acc[nt][3] = e3;
            sum0 += e0 + e1; sum1 += e2 + e3;
        }
    } else {
        int rg0 = gtk[r0], rg1 = gtk[r1];
        #pragma unroll
        for (int nt = 0; nt < 8; nt++) {
            int cA = nt * 8 + t4 * 2;
            int m0 = gtk[cA], m1 = gtk[cA + 1];
            float2 f0 = unpackbf(bF[base0 + nt * 32]);
            float2 f1 = unpackbf(bF[base1 + nt * 32]);
            float e0 = (m0 == rg0) ? __expf(acc[nt][0] + f0.x) : 0.f;
            float e1 = (m1 == rg0) ? __expf(acc[nt][1] + f0.y) : 0.f;
            float e2 = (m0 == rg1) ? __expf(acc[nt][2] + f1.x) : 0.f;
            float e3 = (m1 == rg1) ? __expf(acc[nt][3] + f1.y) : 0.f;
            acc[nt][0] = e0; acc[nt][1] = e1; acc[nt][2] = e2; acc[nt][3] = e3;
            sum0 += e0 + e1; sum1 += e2 + e3;
        }
    }
    sum0 += __shfl_xor_sync(0xffffffff, sum0, 1);
    sum0 += __shfl_xor_sync(0xffffffff, sum0, 2);
    sum1 += __shfl_xor_sync(0xffffffff, sum1, 1);
    sum1 += __shfl_xor_sync(0xffffffff, sum1, 2);
    float inv0 = 1.f / sum0;
    float inv1 = 1.f / sum1;

    // ---- O = P @ V  (S frags -> A frags; V^T in smem as B)
    float out[3][4];
    #pragma unroll
    for (int nv = 0; nv < 3; nv++)
        #pragma unroll
        for (int r = 0; r < 4; r++) out[nv][r] = 0.f;

    #pragma unroll
    for (int ksP = 0; ksP < 4; ksP++) {
        uint32_t a[4];
        a[0] = packbf(acc[2 * ksP    ][0], acc[2 * ksP    ][1]);
        a[1] = packbf(acc[2 * ksP    ][2], acc[2 * ksP    ][3]);
        a[2] = packbf(acc[2 * ksP + 1][0], acc[2 * ksP + 1][1]);
        a[3] = packbf(acc[2 * ksP + 1][2], acc[2 * ksP + 1][3]);
        #pragma unroll
        for (int nv = 0; nv < 3; nv++) {
            uint32_t b[2];
            b[0] = VtU[(h * 24 + nv * 8 + g) * 36 + ksP * 8 + t4    ];
            b[1] = VtU[(h * 24 + nv * 8 + g) * 36 + ksP * 8 + t4 + 4];
            mma_bf16(out[nv], a, b);
        }
    }

    // ---- write O (normalize by row sums)
    uint32_t* attU = (uint32_t*)g_att;
    size_t tok0 = (size_t)bn * NWT + r0;
    size_t tok1 = (size_t)bn * NWT + r1;
    #pragma unroll
    for (int nv = 0; nv < 3; nv++) {
        int col = h * 24 + nv * 8 + t4 * 2;
        attU[(tok0 * 96 + col) >> 1] = packbf(out[nv][0] * inv0, out[nv][1] * inv0);
        attU[(tok1 * 96 + col) >> 1] = packbf(out[nv][2] * inv1, out[nv][3] * inv1);
    }
}

// ============================================================
// K3: proj GEMM + window reverse + roll + residual + LN2
// ============================================================
__global__ void __launch_bounds__(256)
k_proj(const float* __restrict__ x, const float* __restrict__ pbias,
       const float* __restrict__ g2, const float* __restrict__ b2)
{
    extern __shared__ char smem[];
    uint32_t* As = (uint32_t*)smem;
    uint32_t* Bs = (uint32_t*)(smem + 26624);
    float* xs    = (float*)smem;
    int*   sprow = (int*)(smem + 49664);
    float* smu   = (float*)(smem + 50176);
    float* srs   = (float*)(smem + 50688);
    float* sg2   = (float*)(smem + 51200);
    float* sb2   = (float*)(smem + 51584);

    int tid = threadIdx.x;
    if (tid < 96) { sg2[tid] = g2[tid]; sb2[tid] = b2[tid]; }

    size_t bm = (size_t)blockIdx.x * 128;
    stage_A96(g_att, bm, As, tid);
    stage_B96(g_wproj, 0, Bs, tid);
    __syncthreads();

    int warp = tid >> 5, lane = tid & 31, g = lane >> 2, t4 = lane & 3;
    int wm = warp >> 1, wn = warp & 1;

    float acc[2][6][4];
    #pragma unroll
    for (int i = 0; i < 2; i++)
        #pragma unroll
        for (int j = 0; j < 6; j++)
            #pragma unroll
            for (int r = 0; r < 4; r++) acc[i][j][r] = 0.f;
    mma_tile96(As, Bs, acc, g, t4, wm, wn);
    __syncthreads();

    #pragma unroll
    for (int mt = 0; mt < 2; mt++)
        #pragma unroll
        for (int nt = 0; nt < 6; nt++) {
            int cl = wn * 48 + nt * 8 + t4 * 2;
            #pragma unroll
            for (int half = 0; half < 2; half++) {
                int rl = wm * 32 + mt * 16 + g + half * 8;
                xs[rl * 97 + cl    ] = acc[mt][nt][half * 2 + 0] + pbias[cl];
                xs[rl * 97 + cl + 1] = acc[mt][nt][half * 2 + 1] + pbias[cl + 1];
            }
        }
    __syncthreads();

    int t = tid & 127;
    int b, d, h, w;
    decode_tok((int)bm + t, b, d, h, w);
    int spoff = d * 4096 + h * 64 + w;
    size_t xbase = ((size_t)b * 96) * SP + spoff;
    if (tid < 128) sprow[tid] = b * SP + spoff;
    int c0 = tid >> 7;
    for (int c = c0; c < 96; c += 2)
        xs[t * 97 + c] += x[xbase + (size_t)c * SP];
    __syncthreads();

    if (tid < 128) {
        const float* row = xs + tid * 97;
        float s = 0.f, ss = 0.f;
        #pragma unroll
        for (int c = 0; c < 96; c++) { float v = row[c]; s += v; ss += v * v; }
        float mean = s * (1.f / 96.f);
        smu[tid] = mean;
        srs[tid] = rsqrtf(ss * (1.f / 96.f) - mean * mean + 1e-5f);
    }
    __syncthreads();

    #pragma unroll
    for (int tk = 0; tk < 16; tk++) {
        int tt = warp * 16 + tk;
        size_t row = (size_t)sprow[tt] * 96;
        float mu = smu[tt], rs = srs[tt];
        #pragma unroll
        for (int rep = 0; rep < 3; rep++) {
            int c = lane + rep * 32;
            float v = xs[tt * 97 + c];
            g_x2[row + c] = v;
            g_hn[row + c] = __float2bfloat16_rn((v - mu) * rs * sg2[c] + sb2[c]);
        }
    }
}

// ============================================================
// K4: fc1 GEMM + GELU
// ============================================================
__global__ void __launch_bounds__(256)
k_fc1(const float* __restrict__ f1bias)
{
    extern __shared__ char smem[];
    uint32_t* As = (uint32_t*)smem;
    uint32_t* Bs = (uint32_t*)(smem + 26624);

    int tid = threadIdx.x;
    size_t bm = (size_t)blockIdx.x * 128;
    stage_A96(g_hn, bm, As, tid);

    int warp = tid >> 5, lane = tid & 31, g = lane >> 2, t4 = lane & 3;
    int wm = warp >> 1, wn = warp & 1;

    for (int bt = 0; bt < 4; bt++) {
        if (bt) __syncthreads();
        stage_B96(g_wfc1, bt * 96, Bs, tid);
        __syncthreads();
        float acc[2][6][4];
        #pragma unroll
        for (int i = 0; i < 2; i++)
            #pragma unroll
            for (int j = 0; j < 6; j++)
                #pragma unroll
                for (int r = 0; r < 4; r++) acc[i][j][r] = 0.f;
        mma_tile96(As, Bs, acc, g, t4, wm, wn);
        #pragma unroll
        for (int mt = 0; mt < 2; mt++)
            #pragma unroll
            for (int nt = 0; nt < 6; nt++) {
                int ncol = wn * 48 + nt * 8 + t4 * 2;
                #pragma unroll
                for (int half = 0; half < 2; half++) {
                    size_t row = bm + wm * 32 + mt * 16 + g + half * 8;
                    float v0 = acc[mt][nt][half * 2 + 0] + f1bias[bt * 96 + ncol];
                    float v1 = acc[mt][nt][half * 2 + 1] + f1bias[bt * 96 + ncol + 1];
                    v0 = 0.5f * v0 * (1.f + erff(v0 * 0.70710678118654752f));
                    v1 = 0.5f * v1 * (1.f + erff(v1 * 0.70710678118654752f));
                    *(uint32_t*)&g_m1[row * 384 + bt * 96 + ncol] = packbf(v0, v1);
                }
            }
    }
}

// ============================================================
// K5: fc2 GEMM (K=384) + residual + transpose to out
// ============================================================
__global__ void __launch_bounds__(256)
k_fc2(const float* __restrict__ f2bias, float* __restrict__ out)
{
    extern __shared__ char smem[];
    uint32_t* As = (uint32_t*)smem;
    uint32_t* Bs = (uint32_t*)(smem + 26624);
    float* sout  = (float*)smem;

    int tid = threadIdx.x;
    size_t bm = (size_t)blockIdx.x * 128;
    int warp = tid >> 5, lane = tid & 31, g = lane >> 2, t4 = lane & 3;
    int wm = warp >> 1, wn = warp & 1;

    float acc[2][6][4];
    #pragma unroll
    for (int i = 0; i < 2; i++)
        #pragma unroll
        for (int j = 0; j < 6; j++)
            #pragma unroll
            for (int r = 0; r < 4; r++) acc[i][j][r] = 0.f;

    for (int kc = 0; kc < 4; kc++) {
        if (kc) __syncthreads();
        int k0 = kc * 96;
        for (int i = tid; i < 128 * 12; i += 256) {
            int row = i / 12, q = i - row * 12;
            ((uint4*)&As[row * PITCH])[q] = ((const uint4*)(g_m1 + (bm + row) * 384 + k0))[q];
        }
        for (int i = tid; i < 96 * 12; i += 256) {
            int row = i / 12, q = i - row * 12;
            ((uint4*)&Bs[row * PITCH])[q] = ((const uint4*)(g_wfc2 + (size_t)row * 384 + k0))[q];
        }
        __syncthreads();
        mma_tile96(As, Bs, acc, g, t4, wm, wn);
    }
    __syncthreads();

    int b   = (int)(bm >> 17);
    int sp0 = (int)(bm & (SP - 1));

    #pragma unroll
    for (int p = 0; p < 2; p++) {
        if (wn == p) {
            #pragma unroll
            for (int mt = 0; mt < 2; mt++)
                #pragma unroll
                for (int nt = 0; nt < 6; nt++) {
                    int cl = nt * 8 + t4 * 2;
                    #pragma unroll
                    for (int half = 0; half < 2; half++) {
                        int rl = wm * 32 + mt * 16 + g + half * 8;
                        float2 xv = *(const float2*)&g_x2[(bm + rl) * 96 + p * 48 + cl];
                        sout[(cl    ) * 132 + rl] = acc[mt][nt][half * 2 + 0] + f2bias[p * 48 + cl    ] + xv.x;
                        sout[(cl + 1) * 132 + rl] = acc[mt][nt][half * 2 + 1] + f2bias[p * 48 + cl + 1] + xv.y;
                    }
                }
        }
        __syncthreads();
        for (int i = tid; i < 48 * 128; i += 256) {
            int c = i >> 7, tk = i & 127;
            out[((size_t)b * 96 + p * 48 + c) * SP + sp0 + tk] = sout[c * 132 + tk];
        }
        __syncthreads();
    }
}

// ============================================================
// launch
// ============================================================
extern "C" void kernel_launch(void* const* d_in, const int* in_sizes, int n_in,
                              void* d_out, int out_size)
{
    const float* x    = (const float*)d_in[0];
    const float* n1g  = (const float*)d_in[1];
    const float* n1b  = (const float*)d_in[2];
    const float* qkvw = (const float*)d_in[3];
    const float* qkvb = (const float*)d_in[4];
    const float* rpb  = (const float*)d_in[5];
    const float* pw   = (const float*)d_in[6];
    const float* pb   = (const float*)d_in[7];
    const float* n2g  = (const float*)d_in[8];
    const float* n2b  = (const float*)d_in[9];
    const float* f1w  = (const float*)d_in[10];
    const float* f1b  = (const float*)d_in[11];
    const float* f2w  = (const float*)d_in[12];
    const float* f2b  = (const float*)d_in[13];
    float* out = (float*)d_out;

    static int smem_set = 0;
    if (!smem_set) {
        cudaFuncSetAttribute(k_qkv,  cudaFuncAttributeMaxDynamicSharedMemorySize, 48 * 1024);
        cudaFuncSetAttribute(k_attn, cudaFuncAttributeMaxDynamicSharedMemorySize, AT_SIZE);
        cudaFuncSetAttribute(k_proj, cudaFuncAttributeMaxDynamicSharedMemorySize, 52 * 1024);
        cudaFuncSetAttribute(k_fc1,  cudaFuncAttributeMaxDynamicSharedMemorySize, 47 * 1024);
        cudaFuncSetAttribute(k_fc2,  cudaFuncAttributeMaxDynamicSharedMemorySize, 47 * 1024);
        smem_set = 1;
    }

    const int SZ_QKV  = 46592 + 768;
    const int SZ_PROJ = 51968;
    const int SZ_GEMM = 46592;

    k_wconv<<<432, 256>>>(qkvw, pw, f1w, f2w);
    k_bias <<<32, 256>>>(rpb);
    k_qkv <<<NTOK / 128, 256, SZ_QKV >>>(x, n1g, n1b, qkvb);
    k_attn<<<BATCH * NWIN, 512, AT_SIZE>>>();
    k_proj<<<NTOK / 128, 256, SZ_PROJ>>>(x, pb, n2g, n2b);
    k_fc1 <<<NTOK / 128, 256, SZ_GEMM>>>(f1b);
    k_fc2 <<<NTOK / 128, 256, SZ_GEMM>>>(f2b, out);
}